// round 2
// baseline (speedup 1.0000x reference)
#include <cuda_runtime.h>
#include <cstdint>

// ----------------------------- problem constants -----------------------------
#define M_DIM 8192
#define N_DIM 4096
#define K_DIM 4096
#define FP8MAX 448.0f
#define EPSV 1e-12f

// ----------------------------- GEMM tiling ----------------------------------
#define BM 128
#define BN 128
#define BK 64                   // K bytes (fp8 elems) per stage
#define STAGES 6
#define KT (K_DIM / BK)         // 64 k-tiles

// smem: per stage A[128][64B] + B[128][64B] = 16384 B = 4096 words
#define STG_WORDS 4096
#define B_OFF_WORDS 2048
#define SMEM_BYTES (STAGES * STG_WORDS * 4)   // 98304

// ----------------------------- scratch (static device mem) ------------------
__device__ __align__(256) uint8_t g_Xq[(size_t)M_DIM * K_DIM];
__device__ __align__(256) uint8_t g_Wq[(size_t)N_DIM * K_DIM];
__device__ __align__(16) float g_Xs[M_DIM];
__device__ __align__(16) float g_Ws[N_DIM];

// ----------------------------- PTX helpers ----------------------------------
__device__ __forceinline__ uint32_t smem_u32(const void* p) {
    uint32_t a;
    asm("{ .reg .u64 t; cvta.to.shared.u64 t, %1; cvt.u32.u64 %0, t; }"
        : "=r"(a) : "l"(p));
    return a;
}

__device__ __forceinline__ void cp16(uint32_t s, const void* g) {
    asm volatile("cp.async.cg.shared.global [%0], [%1], 16;" :: "r"(s), "l"(g));
}
__device__ __forceinline__ void cp_commit() {
    asm volatile("cp.async.commit_group;" ::: "memory");
}
template <int N>
__device__ __forceinline__ void cp_wait() {
    asm volatile("cp.async.wait_group %0;" :: "n"(N) : "memory");
}

__device__ __forceinline__ void mma_fp8(float* d, const uint32_t* a, const uint32_t* b) {
    asm volatile(
        "mma.sync.aligned.m16n8k32.row.col.f32.e4m3.e4m3.f32 "
        "{%0,%1,%2,%3}, {%4,%5,%6,%7}, {%8,%9}, {%0,%1,%2,%3};"
        : "+f"(d[0]), "+f"(d[1]), "+f"(d[2]), "+f"(d[3])
        : "r"(a[0]), "r"(a[1]), "r"(a[2]), "r"(a[3]), "r"(b[0]), "r"(b[1]));
}

// pack two f32 -> e4m3x2 (lo in low byte), RN + satfinite
__device__ __forceinline__ uint16_t cvt_e4m3x2(float lo, float hi) {
    uint16_t r;
    asm volatile("cvt.rn.satfinite.e4m3x2.f32 %0, %1, %2;" : "=h"(r) : "f"(hi), "f"(lo));
    return r;
}

// ----------------------------- weight quant ---------------------------------
__global__ void __launch_bounds__(256) wquant_kernel(const float* __restrict__ w) {
    const int row = blockIdx.x;
    const float4* wr = (const float4*)(w + (size_t)row * K_DIM);

    float4 v[4];
    float mx = 0.f;
#pragma unroll
    for (int i = 0; i < 4; i++) {
        v[i] = wr[threadIdx.x + i * 256];
        mx = fmaxf(mx, fmaxf(fmaxf(fabsf(v[i].x), fabsf(v[i].y)),
                             fmaxf(fabsf(v[i].z), fabsf(v[i].w))));
    }
    __shared__ float red[8];
    __shared__ float s_scale;
#pragma unroll
    for (int o = 16; o; o >>= 1) mx = fmaxf(mx, __shfl_xor_sync(0xffffffffu, mx, o));
    if ((threadIdx.x & 31) == 0) red[threadIdx.x >> 5] = mx;
    __syncthreads();
    if (threadIdx.x == 0) {
        float m = red[0];
#pragma unroll
        for (int j = 1; j < 8; j++) m = fmaxf(m, red[j]);
        float sc = __fdiv_rn(fmaxf(m, EPSV), FP8MAX);
        s_scale = sc;
        g_Ws[row] = sc;
    }
    __syncthreads();
    const float sc = s_scale;

    uint32_t* oq = (uint32_t*)(g_Wq + (size_t)row * K_DIM);
#pragma unroll
    for (int i = 0; i < 4; i++) {
        uint16_t lo = cvt_e4m3x2(__fdiv_rn(v[i].x, sc), __fdiv_rn(v[i].y, sc));
        uint16_t hi = cvt_e4m3x2(__fdiv_rn(v[i].z, sc), __fdiv_rn(v[i].w, sc));
        oq[threadIdx.x + i * 256] = (uint32_t)lo | ((uint32_t)hi << 16);
    }
}

// ----------------------------- activation quant -----------------------------
__global__ void __launch_bounds__(256) aquant_kernel(const float* __restrict__ x) {
    const int row = blockIdx.x;
    const float4* xr = (const float4*)(x + (size_t)row * K_DIM);

    float a0[4], a1[4], a2[4], a3[4];
    float mx = 0.f;
#pragma unroll
    for (int i = 0; i < 4; i++) {
        float4 v = xr[threadIdx.x + i * 256];
        float r0 = fmaxf(v.x, 0.f), r1 = fmaxf(v.y, 0.f);
        float r2 = fmaxf(v.z, 0.f), r3 = fmaxf(v.w, 0.f);
        a0[i] = r0 * r0; a1[i] = r1 * r1; a2[i] = r2 * r2; a3[i] = r3 * r3;
        mx = fmaxf(mx, fmaxf(fmaxf(a0[i], a1[i]), fmaxf(a2[i], a3[i])));
    }
    __shared__ float red[8];
    __shared__ float s_scale;
#pragma unroll
    for (int o = 16; o; o >>= 1) mx = fmaxf(mx, __shfl_xor_sync(0xffffffffu, mx, o));
    if ((threadIdx.x & 31) == 0) red[threadIdx.x >> 5] = mx;
    __syncthreads();
    if (threadIdx.x == 0) {
        float m = red[0];
#pragma unroll
        for (int j = 1; j < 8; j++) m = fmaxf(m, red[j]);
        float sc = __fdiv_rn(fmaxf(m, EPSV), FP8MAX);
        s_scale = sc;
        g_Xs[row] = sc;
    }
    __syncthreads();
    const float sc = s_scale;

    uint32_t* oq = (uint32_t*)(g_Xq + (size_t)row * K_DIM);
#pragma unroll
    for (int i = 0; i < 4; i++) {
        float b0 = a0[i], b1 = a1[i], b2 = a2[i], b3 = a3[i];
        // first argmax (ties -> lower index, matches lax.top_k)
        int i1 = 0; float m1 = b0;
        if (b1 > m1) { m1 = b1; i1 = 1; }
        if (b2 > m1) { m1 = b2; i1 = 2; }
        if (b3 > m1) { m1 = b3; i1 = 3; }
        float c0 = (i1 == 0) ? -1.f : b0;
        float c1 = (i1 == 1) ? -1.f : b1;
        float c2 = (i1 == 2) ? -1.f : b2;
        float c3 = (i1 == 3) ? -1.f : b3;
        int i2 = 0; float m2 = c0;
        if (c1 > m2) { m2 = c1; i2 = 1; }
        if (c2 > m2) { m2 = c2; i2 = 2; }
        if (c3 > m2) { m2 = c3; i2 = 3; }

        float q0 = (i1 == 0 || i2 == 0) ? __fdiv_rn(b0, sc) : 0.f;
        float q1 = (i1 == 1 || i2 == 1) ? __fdiv_rn(b1, sc) : 0.f;
        float q2 = (i1 == 2 || i2 == 2) ? __fdiv_rn(b2, sc) : 0.f;
        float q3 = (i1 == 3 || i2 == 3) ? __fdiv_rn(b3, sc) : 0.f;

        uint16_t lo = cvt_e4m3x2(q0, q1);
        uint16_t hi = cvt_e4m3x2(q2, q3);
        oq[threadIdx.x + i * 256] = (uint32_t)lo | ((uint32_t)hi << 16);
    }
}

// ----------------------------- fp8 GEMM (mma.sync, legacy TC path) ----------
// 128x128 CTA tile, 8 warps in 2x4 (warp tile 64x32), BK=64 stages, 6-deep
// cp.async ring. 16B-chunk XOR swizzle: chunk' = chunk ^ ((row>>1)&3) makes
// all fragment LDS.32 reads conflict-free.
__global__ void __launch_bounds__(256) gemm_kernel(float* __restrict__ out) {
    extern __shared__ uint32_t sm[];
    const uint32_t sb = smem_u32(sm);
    const int tid = threadIdx.x;
    const int wid = tid >> 5;
    const int lane = tid & 31;
    const int gid = lane >> 2;   // 0..7
    const int t4 = lane & 3;     // 0..3
    const int wm = (wid >> 2) * 64;   // warp M offset (0/64)
    const int wn = (wid & 3) * 32;    // warp N offset (0/32/64/96)
    const int m0 = blockIdx.y * BM;
    const int n0 = blockIdx.x * BN;

    // producer mapping: thread -> (row, 2 chunks of 16B)
    const int lr = tid >> 1;            // 0..127
    const int lcb = (tid & 1) * 2;      // chunk base 0 or 2
    const int pswz = (lr >> 1) & 3;
    const uint8_t* gA = g_Xq + (size_t)(m0 + lr) * K_DIM + lcb * 16;
    const uint8_t* gB = g_Wq + (size_t)(n0 + lr) * K_DIM + lcb * 16;
    // smem byte addrs of this thread's two A chunks / two B chunks (stage 0)
    const uint32_t sA0 = sb + (lr * 16 + ((lcb ^ pswz) << 2)) * 4;
    const uint32_t sA1 = sb + (lr * 16 + (((lcb + 1) ^ pswz) << 2)) * 4;
    const uint32_t sB0 = sA0 + B_OFF_WORDS * 4;
    const uint32_t sB1 = sA1 + B_OFF_WORDS * 4;

    float acc[4][4][4];
#pragma unroll
    for (int i = 0; i < 4; i++)
#pragma unroll
        for (int j = 0; j < 4; j++)
#pragma unroll
            for (int c = 0; c < 4; c++) acc[i][j][c] = 0.f;

    // fragment smem word index
#define AWRD(st, r, c, w) ((st) * STG_WORDS + (r) * 16 + ((((c) ^ (((r) >> 1) & 3))) << 2) + (w))
#define BWRD(st, r, c, w) (AWRD(st, r, c, w) + B_OFF_WORDS)

    // ---- prologue: fill STAGES-1 stages ----
#pragma unroll
    for (int s = 0; s < STAGES - 1; s++) {
        const size_t kb = (size_t)s * BK;
        const uint32_t so = s * STG_WORDS * 4;
        cp16(sA0 + so, gA + kb);
        cp16(sA1 + so, gA + kb + 16);
        cp16(sB0 + so, gB + kb);
        cp16(sB1 + so, gB + kb + 16);
        cp_commit();
    }

    // ---- main loop ----
#pragma unroll 1
    for (int kt = 0; kt < KT; kt++) {
        cp_wait<STAGES - 2>();
        __syncthreads();

        // issue loads for stage kt+STAGES-1 (buffer freed at iter kt-1)
        if (kt + STAGES - 1 < KT) {
            const int ls = (kt + STAGES - 1) % STAGES;
            const size_t kb = (size_t)(kt + STAGES - 1) * BK;
            const uint32_t so = ls * STG_WORDS * 4;
            cp16(sA0 + so, gA + kb);
            cp16(sA1 + so, gA + kb + 16);
            cp16(sB0 + so, gB + kb);
            cp16(sB1 + so, gB + kb + 16);
        }
        cp_commit();

        const int st = kt % STAGES;
#pragma unroll
        for (int j = 0; j < 2; j++) {     // two k32 steps per stage
            uint32_t a[4][4], b[4][2];
#pragma unroll
            for (int mi = 0; mi < 4; mi++) {
                const int r0 = wm + mi * 16 + gid;
                a[mi][0] = sm[AWRD(st, r0,     2 * j,     t4)];
                a[mi][1] = sm[AWRD(st, r0 + 8, 2 * j,     t4)];
                a[mi][2] = sm[AWRD(st, r0,     2 * j + 1, t4)];
                a[mi][3] = sm[AWRD(st, r0 + 8, 2 * j + 1, t4)];
            }
#pragma unroll
            for (int ni = 0; ni < 4; ni++) {
                const int rn = wn + ni * 8 + gid;
                b[ni][0] = sm[BWRD(st, rn, 2 * j,     t4)];
                b[ni][1] = sm[BWRD(st, rn, 2 * j + 1, t4)];
            }
#pragma unroll
            for (int mi = 0; mi < 4; mi++)
#pragma unroll
                for (int ni = 0; ni < 4; ni++)
                    mma_fp8(acc[mi][ni], a[mi], b[ni]);
        }
    }

    // ---- epilogue: rescale + store ----
#pragma unroll
    for (int mi = 0; mi < 4; mi++) {
        const int r0 = m0 + wm + mi * 16 + gid;
        const float xs0 = g_Xs[r0];
        const float xs1 = g_Xs[r0 + 8];
#pragma unroll
        for (int ni = 0; ni < 4; ni++) {
            const int c = n0 + wn + ni * 8 + t4 * 2;
            const float ws0 = g_Ws[c];
            const float ws1 = g_Ws[c + 1];
            float2 o0, o1;
            o0.x = acc[mi][ni][0] * xs0 * ws0;
            o0.y = acc[mi][ni][1] * xs0 * ws1;
            o1.x = acc[mi][ni][2] * xs1 * ws0;
            o1.y = acc[mi][ni][3] * xs1 * ws1;
            *(float2*)(out + (size_t)r0 * N_DIM + c) = o0;
            *(float2*)(out + (size_t)(r0 + 8) * N_DIM + c) = o1;
        }
    }
#undef AWRD
#undef BWRD
}

// ----------------------------- launch ---------------------------------------
extern "C" void kernel_launch(void* const* d_in, const int* in_sizes, int n_in,
                              void* d_out, int out_size) {
    const float* x = (const float*)d_in[0];   // [8192, 4096] f32
    const float* w = (const float*)d_in[1];   // [4096, 4096] f32
    float* out = (float*)d_out;               // [8192, 4096] f32
    (void)in_sizes; (void)n_in; (void)out_size;

    cudaFuncSetAttribute(gemm_kernel,
                         cudaFuncAttributeMaxDynamicSharedMemorySize, SMEM_BYTES);

    wquant_kernel<<<N_DIM, 256>>>(w);
    aquant_kernel<<<M_DIM, 256>>>(x);
    gemm_kernel<<<dim3(N_DIM / BN, M_DIM / BM), 256, SMEM_BYTES>>>(out);
}

// round 4
// speedup vs baseline: 1.2557x; 1.2557x over previous
#include <cuda_runtime.h>
#include <cstdint>

// ----------------------------- problem constants -----------------------------
#define M_DIM 8192
#define N_DIM 4096
#define K_DIM 4096
#define FP8MAX 448.0f
#define EPSV 1e-12f

// ----------------------------- GEMM tiling ----------------------------------
#define BM 128
#define BN 128
#define BK 64                   // K bytes (fp8 elems) per stage
#define STAGES 6
#define KT (K_DIM / BK)         // 64 k-tiles

// per-stage smem: A[128][64B] + B[128][64B] = 16 KB
#define STG_BYTES 16384
#define B_OFF 8192
#define SMEM_BYTES (STAGES * STG_BYTES)   // 98304

// ----------------------------- scratch (static device mem) ------------------
__device__ __align__(256) uint8_t g_Xq[(size_t)M_DIM * K_DIM];
__device__ __align__(256) uint8_t g_Wq[(size_t)N_DIM * K_DIM];
__device__ __align__(16) float g_Xs[M_DIM];
__device__ __align__(16) float g_Ws[N_DIM];

// ----------------------------- PTX helpers ----------------------------------
__device__ __forceinline__ uint32_t smem_u32(const void* p) {
    uint32_t a;
    asm("{ .reg .u64 t; cvta.to.shared.u64 t, %1; cvt.u32.u64 %0, t; }"
        : "=r"(a) : "l"(p));
    return a;
}
__device__ __forceinline__ void cp16(uint32_t s, const void* g) {
    asm volatile("cp.async.cg.shared.global [%0], [%1], 16;" :: "r"(s), "l"(g));
}
__device__ __forceinline__ void cp_commit() {
    asm volatile("cp.async.commit_group;" ::: "memory");
}
template <int N>
__device__ __forceinline__ void cp_wait() {
    asm volatile("cp.async.wait_group %0;" :: "n"(N) : "memory");
}
__device__ __forceinline__ void ldsm4(uint32_t* r, uint32_t addr) {
    asm volatile("ldmatrix.sync.aligned.m8n8.x4.shared.b16 {%0,%1,%2,%3}, [%4];"
                 : "=r"(r[0]), "=r"(r[1]), "=r"(r[2]), "=r"(r[3]) : "r"(addr));
}
__device__ __forceinline__ void mma_fp8(float* d, const uint32_t* a,
                                        uint32_t b0, uint32_t b1) {
    asm volatile(
        "mma.sync.aligned.m16n8k32.row.col.f32.e4m3.e4m3.f32 "
        "{%0,%1,%2,%3}, {%4,%5,%6,%7}, {%8,%9}, {%0,%1,%2,%3};"
        : "+f"(d[0]), "+f"(d[1]), "+f"(d[2]), "+f"(d[3])
        : "r"(a[0]), "r"(a[1]), "r"(a[2]), "r"(a[3]), "r"(b0), "r"(b1));
}
// pack two f32 -> e4m3x2 (lo in low byte), RN + satfinite
__device__ __forceinline__ uint16_t cvt_e4m3x2(float lo, float hi) {
    uint16_t r;
    asm volatile("cvt.rn.satfinite.e4m3x2.f32 %0, %1, %2;" : "=h"(r) : "f"(hi), "f"(lo));
    return r;
}

// ----------------------------- weight quant ---------------------------------
__global__ void __launch_bounds__(256) wquant_kernel(const float* __restrict__ w) {
    const int row = blockIdx.x;
    const float4* wr = (const float4*)(w + (size_t)row * K_DIM);

    float4 v[4];
    float mx = 0.f;
#pragma unroll
    for (int i = 0; i < 4; i++) {
        v[i] = wr[threadIdx.x + i * 256];
        mx = fmaxf(mx, fmaxf(fmaxf(fabsf(v[i].x), fabsf(v[i].y)),
                             fmaxf(fabsf(v[i].z), fabsf(v[i].w))));
    }
    __shared__ float red[8];
    __shared__ float s_scale;
#pragma unroll
    for (int o = 16; o; o >>= 1) mx = fmaxf(mx, __shfl_xor_sync(0xffffffffu, mx, o));
    if ((threadIdx.x & 31) == 0) red[threadIdx.x >> 5] = mx;
    __syncthreads();
    if (threadIdx.x == 0) {
        float m = red[0];
#pragma unroll
        for (int j = 1; j < 8; j++) m = fmaxf(m, red[j]);
        float sc = __fdiv_rn(fmaxf(m, EPSV), FP8MAX);
        s_scale = sc;
        g_Ws[row] = sc;
    }
    __syncthreads();
    const float sc = s_scale;

    uint32_t* oq = (uint32_t*)(g_Wq + (size_t)row * K_DIM);
#pragma unroll
    for (int i = 0; i < 4; i++) {
        uint16_t lo = cvt_e4m3x2(__fdiv_rn(v[i].x, sc), __fdiv_rn(v[i].y, sc));
        uint16_t hi = cvt_e4m3x2(__fdiv_rn(v[i].z, sc), __fdiv_rn(v[i].w, sc));
        oq[threadIdx.x + i * 256] = (uint32_t)lo | ((uint32_t)hi << 16);
    }
}

// ----------------------------- activation quant -----------------------------
__global__ void __launch_bounds__(256) aquant_kernel(const float* __restrict__ x) {
    const int row = blockIdx.x;
    const float4* xr = (const float4*)(x + (size_t)row * K_DIM);

    float a0[4], a1[4], a2[4], a3[4];
    float mx = 0.f;
#pragma unroll
    for (int i = 0; i < 4; i++) {
        float4 v = xr[threadIdx.x + i * 256];
        float r0 = fmaxf(v.x, 0.f), r1 = fmaxf(v.y, 0.f);
        float r2 = fmaxf(v.z, 0.f), r3 = fmaxf(v.w, 0.f);
        a0[i] = r0 * r0; a1[i] = r1 * r1; a2[i] = r2 * r2; a3[i] = r3 * r3;
        mx = fmaxf(mx, fmaxf(fmaxf(a0[i], a1[i]), fmaxf(a2[i], a3[i])));
    }
    __shared__ float red[8];
    __shared__ float s_scale;
#pragma unroll
    for (int o = 16; o; o >>= 1) mx = fmaxf(mx, __shfl_xor_sync(0xffffffffu, mx, o));
    if ((threadIdx.x & 31) == 0) red[threadIdx.x >> 5] = mx;
    __syncthreads();
    if (threadIdx.x == 0) {
        float m = red[0];
#pragma unroll
        for (int j = 1; j < 8; j++) m = fmaxf(m, red[j]);
        float sc = __fdiv_rn(fmaxf(m, EPSV), FP8MAX);
        s_scale = sc;
        g_Xs[row] = sc;
    }
    __syncthreads();
    const float sc = s_scale;

    uint32_t* oq = (uint32_t*)(g_Xq + (size_t)row * K_DIM);
#pragma unroll
    for (int i = 0; i < 4; i++) {
        float b0 = a0[i], b1 = a1[i], b2 = a2[i], b3 = a3[i];
        int i1 = 0; float m1 = b0;
        if (b1 > m1) { m1 = b1; i1 = 1; }
        if (b2 > m1) { m1 = b2; i1 = 2; }
        if (b3 > m1) { m1 = b3; i1 = 3; }
        float c0 = (i1 == 0) ? -1.f : b0;
        float c1 = (i1 == 1) ? -1.f : b1;
        float c2 = (i1 == 2) ? -1.f : b2;
        float c3 = (i1 == 3) ? -1.f : b3;
        int i2 = 0; float m2 = c0;
        if (c1 > m2) { m2 = c1; i2 = 1; }
        if (c2 > m2) { m2 = c2; i2 = 2; }
        if (c3 > m2) { m2 = c3; i2 = 3; }

        float q0 = (i1 == 0 || i2 == 0) ? __fdiv_rn(b0, sc) : 0.f;
        float q1 = (i1 == 1 || i2 == 1) ? __fdiv_rn(b1, sc) : 0.f;
        float q2 = (i1 == 2 || i2 == 2) ? __fdiv_rn(b2, sc) : 0.f;
        float q3 = (i1 == 3 || i2 == 3) ? __fdiv_rn(b3, sc) : 0.f;

        uint16_t lo = cvt_e4m3x2(q0, q1);
        uint16_t hi = cvt_e4m3x2(q2, q3);
        oq[threadIdx.x + i * 256] = (uint32_t)lo | ((uint32_t)hi << 16);
    }
}

// ----------------------------- dense fp8 GEMM (ldmatrix + pipelined) --------
// 128x128 CTA tile, 8 warps (2x4), warp tile 64x32, BK=64 stages, 6-deep
// cp.async ring, 2 CTAs/SM. 16B-chunk XOR swizzle: chunk' = chunk ^ ((row>>1)&3);
// within the swizzled offset, chunk index c maps to addr_base ^ (c<<4).
__global__ void __launch_bounds__(256, 2) gemm_kernel(float* __restrict__ out) {
    extern __shared__ uint32_t sm[];
    const uint32_t sb = smem_u32(sm);
    const int tid = threadIdx.x;
    const int wid = tid >> 5;
    const int lane = tid & 31;
    const int gid = lane >> 2;
    const int t4 = lane & 3;
    const int wm = (wid >> 2) * 64;
    const int wn = (wid & 3) * 32;
    const int m0 = blockIdx.y * BM;
    const int n0 = blockIdx.x * BN;

    // ---- ldmatrix lane offsets (relative to smem base, stage 0, j=0) ----
    // A: lanes 0-7 -> rows 0-7 chunk0 (a0), 8-15 -> rows 8-15 chunk0 (a1),
    //    16-23 -> rows 0-7 chunk1 (a2), 24-31 -> rows 8-15 chunk1 (a3)
    const int ar = lane & 15;
    const uint32_t swzA = ((uint32_t)ar >> 1) & 3;
    const uint32_t aAo = (uint32_t)(wm + ar) * 64 +
                         ((((uint32_t)lane >> 4) ^ swzA) << 4);
    // B: lane L -> n-row wn+L, chunk 0 base
    const uint32_t swzB = ((uint32_t)lane >> 1) & 3;
    const uint32_t aBo = B_OFF + (uint32_t)(wn + lane) * 64 + (swzB << 4);

    // ---- producer mapping: thread -> (row lr, chunks 2h,2h+1) ----
    const int lr = tid >> 1;
    const int half = tid & 1;
    const uint8_t* pA = g_Xq + (size_t)(m0 + lr) * K_DIM + half * 32;
    const uint8_t* pB = g_Wq + (size_t)(n0 + lr) * K_DIM + half * 32;
    const uint32_t swzP = ((uint32_t)lr >> 1) & 3;
    const uint32_t sPo = (uint32_t)lr * 64 + ((((uint32_t)half * 2) ^ swzP) << 4);

    float acc[4][4][4];
#pragma unroll
    for (int i = 0; i < 4; i++)
#pragma unroll
        for (int j = 0; j < 4; j++)
#pragma unroll
            for (int c = 0; c < 4; c++) acc[i][j][c] = 0.f;

    // ---- prologue: fill STAGES-1 stages ----
#pragma unroll
    for (int s = 0; s < STAGES - 1; s++) {
        const uint32_t po = s * STG_BYTES;
        const size_t gk = (size_t)s * BK;
        cp16(sb + sPo + po, pA + gk);
        cp16(sb + (sPo ^ 0x10) + po, pA + gk + 16);
        cp16(sb + (sPo + B_OFF) + po, pB + gk);
        cp16(sb + ((sPo + B_OFF) ^ 0x10) + po, pB + gk + 16);
        cp_commit();
    }

    // ---- main loop ----
#pragma unroll 1
    for (int kt = 0; kt < KT; kt++) {
        cp_wait<STAGES - 2>();
        __syncthreads();

        if (kt + STAGES - 1 < KT) {
            const uint32_t po = ((kt + STAGES - 1) % STAGES) * STG_BYTES;
            const size_t gk = (size_t)(kt + STAGES - 1) * BK;
            cp16(sb + sPo + po, pA + gk);
            cp16(sb + (sPo ^ 0x10) + po, pA + gk + 16);
            cp16(sb + (sPo + B_OFF) + po, pB + gk);
            cp16(sb + ((sPo + B_OFF) ^ 0x10) + po, pB + gk + 16);
        }
        cp_commit();

        const uint32_t co = (kt % STAGES) * STG_BYTES;
        uint32_t af[2][4][4], bf[2][2][4];
        // j=0 fragments
#pragma unroll
        for (int mi = 0; mi < 4; mi++)
            ldsm4(af[0][mi], sb + aAo + co + mi * 1024);
        ldsm4(bf[0][0], sb + aBo + co);
        ldsm4(bf[0][1], sb + (aBo ^ 0x10) + co);
        // j=1 fragments (chunk += 2 -> ^0x20)
#pragma unroll
        for (int mi = 0; mi < 4; mi++)
            ldsm4(af[1][mi], sb + (aAo ^ 0x20) + co + mi * 1024);
        ldsm4(bf[1][0], sb + (aBo ^ 0x20) + co);
        ldsm4(bf[1][1], sb + (aBo ^ 0x30) + co);

#pragma unroll
        for (int j = 0; j < 2; j++)
#pragma unroll
            for (int mi = 0; mi < 4; mi++)
#pragma unroll
                for (int ni = 0; ni < 4; ni++)
                    mma_fp8(acc[mi][ni], af[j][mi], bf[j][0][ni], bf[j][1][ni]);
    }

    // ---- epilogue: rescale + store ----
#pragma unroll
    for (int mi = 0; mi < 4; mi++) {
        const int r0 = m0 + wm + mi * 16 + gid;
        const float xs0 = g_Xs[r0];
        const float xs1 = g_Xs[r0 + 8];
#pragma unroll
        for (int ni = 0; ni < 4; ni++) {
            const int c = n0 + wn + ni * 8 + t4 * 2;
            const float ws0 = g_Ws[c];
            const float ws1 = g_Ws[c + 1];
            float2 o0, o1;
            o0.x = acc[mi][ni][0] * xs0 * ws0;
            o0.y = acc[mi][ni][1] * xs0 * ws1;
            o1.x = acc[mi][ni][2] * xs1 * ws0;
            o1.y = acc[mi][ni][3] * xs1 * ws1;
            *(float2*)(out + (size_t)r0 * N_DIM + c) = o0;
            *(float2*)(out + (size_t)(r0 + 8) * N_DIM + c) = o1;
        }
    }
}

// ----------------------------- launch ---------------------------------------
extern "C" void kernel_launch(void* const* d_in, const int* in_sizes, int n_in,
                              void* d_out, int out_size) {
    const float* x = (const float*)d_in[0];   // [8192, 4096] f32
    const float* w = (const float*)d_in[1];   // [4096, 4096] f32
    float* out = (float*)d_out;               // [8192, 4096] f32
    (void)in_sizes; (void)n_in; (void)out_size;

    cudaFuncSetAttribute(gemm_kernel,
                         cudaFuncAttributeMaxDynamicSharedMemorySize, SMEM_BYTES);

    wquant_kernel<<<N_DIM, 256>>>(w);
    aquant_kernel<<<M_DIM, 256>>>(x);
    gemm_kernel<<<dim3(N_DIM / BN, M_DIM / BM), 256, SMEM_BYTES>>>(out);
}